// round 2
// baseline (speedup 1.0000x reference)
#include <cuda_runtime.h>
#include <math.h>

#define BB 32
#define HWT 12544          // 112*112
#define CC 256
#define HID 32
#define F4_PER_ROW 64      // 256 channels / 4

#define KCTA 64            // CTAs cooperating on one batch
#define PGRP 4             // concurrent batch groups
#define ITERS 8            // batches per group (4*8 = 32)
#define ROWS_CTA 196       // HWT / KCTA
#define ROWS_T 49          // ROWS_CTA / 4 row-groups

__device__ float g_psum[BB][KCTA][CC];
__device__ float g_pmax[BB][KCTA][CC];
__device__ float g_scale[BB][CC];
__device__ int   g_ctr[PGRP][ITERS];
__device__ int   g_flag[PGRP][ITERS];

__global__ void init_kernel() {
    int t = threadIdx.x;
    if (t < PGRP * ITERS) {
        (&g_ctr[0][0])[t] = 0;
        (&g_flag[0][0])[t] = 0;
    }
}

__global__ void __launch_bounds__(256, 2) fused_kernel(
    const float* __restrict__ x,
    const float* __restrict__ w1, const float* __restrict__ b1,
    const float* __restrict__ w2, const float* __restrict__ b2,
    float* __restrict__ out)
{
    const int p   = blockIdx.y;   // group
    const int k   = blockIdx.x;   // CTA within group
    const int tid = threadIdx.x;
    const int c4  = tid & 63;     // float4 channel group
    const int rg  = tid >> 6;     // row group 0..3

    __shared__ float4 s_sum[4][64];
    __shared__ float4 s_mx4[4][64];
    __shared__ float  s_avg[CC];
    __shared__ float  s_max[CC];
    __shared__ float  s_h[2 * HID];
    __shared__ float4 s_scale[64];

    for (int it = 0; it < ITERS; ++it) {
        const int b = p * ITERS + it;
        const size_t row0 = (size_t)b * HWT + (size_t)k * ROWS_CTA + (size_t)rg * ROWS_T;
        const float4* __restrict__ xp = reinterpret_cast<const float4*>(x) + row0 * F4_PER_ROW + c4;

        // ---- Phase 1: pool 49 rows per thread (DRAM read, cached in L2) ----
        float4 s = make_float4(0.f, 0.f, 0.f, 0.f);
        float4 m = make_float4(-INFINITY, -INFINITY, -INFINITY, -INFINITY);
        #pragma unroll 7
        for (int r = 0; r < ROWS_T; ++r) {
            float4 v = xp[(size_t)r * F4_PER_ROW];
            s.x += v.x; s.y += v.y; s.z += v.z; s.w += v.w;
            m.x = fmaxf(m.x, v.x); m.y = fmaxf(m.y, v.y);
            m.z = fmaxf(m.z, v.z); m.w = fmaxf(m.w, v.w);
        }
        s_sum[rg][c4] = s;
        s_mx4[rg][c4] = m;
        __syncthreads();

        if (rg == 0) {
            float4 a0 = s_sum[0][c4], a1 = s_sum[1][c4], a2 = s_sum[2][c4], a3 = s_sum[3][c4];
            float4 b0 = s_mx4[0][c4], b1v = s_mx4[1][c4], b2v = s_mx4[2][c4], b3 = s_mx4[3][c4];
            float4 ss = make_float4(a0.x + a1.x + a2.x + a3.x,
                                    a0.y + a1.y + a2.y + a3.y,
                                    a0.z + a1.z + a2.z + a3.z,
                                    a0.w + a1.w + a2.w + a3.w);
            float4 mm = make_float4(fmaxf(fmaxf(b0.x, b1v.x), fmaxf(b2v.x, b3.x)),
                                    fmaxf(fmaxf(b0.y, b1v.y), fmaxf(b2v.y, b3.y)),
                                    fmaxf(fmaxf(b0.z, b1v.z), fmaxf(b2v.z, b3.z)),
                                    fmaxf(fmaxf(b0.w, b1v.w), fmaxf(b2v.w, b3.w)));
            reinterpret_cast<float4*>(&g_psum[b][k][0])[c4] = ss;
            reinterpret_cast<float4*>(&g_pmax[b][k][0])[c4] = mm;
        }
        __threadfence();       // release partials
        __syncthreads();

        // ---- Phase 2: cross-CTA barrier + MLP (CTA 0 only computes) ----
        if (k == 0) {
            if (tid == 0) {
                atomicAdd(&g_ctr[p][it], 1);
                while (atomicAdd(&g_ctr[p][it], 0) < KCTA) { }
                __threadfence();   // acquire partials
            }
            __syncthreads();

            // reduce K partials for channel `tid`
            float sum = 0.f, mx = -INFINITY;
            #pragma unroll 8
            for (int q = 0; q < KCTA; ++q) {
                sum += __ldcg(&g_psum[b][q][tid]);
                mx = fmaxf(mx, __ldcg(&g_pmax[b][q][tid]));
            }
            s_avg[tid] = sum * (1.0f / (float)HWT);
            s_max[tid] = mx;
            __syncthreads();

            // hidden layer: 64 outputs (2 branches x 32), 4 threads per output
            {
                int oi = tid >> 2;           // 0..63
                int part = tid & 3;
                int j = oi & (HID - 1);
                const float* pool = (oi < HID) ? s_avg : s_max;
                float acc = 0.f;
                #pragma unroll 16
                for (int i = part * 64; i < part * 64 + 64; ++i)
                    acc += pool[i] * w1[i * HID + j];
                acc += __shfl_down_sync(0xffffffffu, acc, 1);
                acc += __shfl_down_sync(0xffffffffu, acc, 2);
                if (part == 0) s_h[oi] = fmaxf(acc + b1[j], 0.f);
            }
            __syncthreads();

            // out layer: out = 2*b2 + (hA+hM) @ w2, then sigmoid
            {
                float acc = 2.0f * b2[tid];
                #pragma unroll
                for (int j = 0; j < HID; ++j)
                    acc += (s_h[j] + s_h[HID + j]) * w2[j * CC + tid];
                float sc = 1.0f / (1.0f + expf(-acc));
                ((float*)s_scale)[tid] = sc;
                g_scale[b][tid] = sc;
            }
            __threadfence();   // release g_scale
            __syncthreads();
            if (tid == 0) atomicExch(&g_flag[p][it], 1);
        } else {
            if (tid == 0) {
                atomicAdd(&g_ctr[p][it], 1);
                while (atomicAdd(&g_flag[p][it], 0) == 0) { }
                __threadfence();   // acquire g_scale
            }
            __syncthreads();
        }

        // ---- Phase 3: scale (x re-read hits L2; streaming hints) ----
        float4 sc4;
        if (k == 0)
            sc4 = s_scale[c4];
        else
            sc4 = __ldcg(reinterpret_cast<const float4*>(&g_scale[b][0]) + c4);

        float4* __restrict__ op = reinterpret_cast<float4*>(out) + row0 * F4_PER_ROW + c4;
        #pragma unroll 7
        for (int r = 0; r < ROWS_T; ++r) {
            float4 v = __ldcs(xp + (size_t)r * F4_PER_ROW);   // last use: evict-first
            v.x *= sc4.x; v.y *= sc4.y; v.z *= sc4.z; v.w *= sc4.w;
            __stcs(op + (size_t)r * F4_PER_ROW, v);           // streaming store
        }
        // no trailing sync needed: next-iter smem writes are fenced by the
        // __syncthreads after phase-1 pooling before any reuse.
    }
}

extern "C" void kernel_launch(void* const* d_in, const int* in_sizes, int n_in,
                              void* d_out, int out_size) {
    const float* x  = (const float*)d_in[0];
    const float* w1 = (const float*)d_in[1];
    const float* b1 = (const float*)d_in[2];
    const float* w2 = (const float*)d_in[3];
    const float* b2 = (const float*)d_in[4];
    float* out = (float*)d_out;

    init_kernel<<<1, 32>>>();
    fused_kernel<<<dim3(KCTA, PGRP), 256>>>(x, w1, b1, w2, b2, out);
}

// round 3
// speedup vs baseline: 1.3478x; 1.3478x over previous
#include <cuda_runtime.h>
#include <math.h>

#define BB 32
#define HWT 12544              // 112*112
#define CC 256
#define HID 32
#define F4_PER_ROW 64          // 256 / 4

#define GROUP 8                // batches per group (8 * 12.85MB = 103MB <= L2)
#define NGRP 4                 // 4 groups * 8 = 32 batches
#define KCTA 64                // CTAs per batch in pool
#define ROWS_CTA 196           // HWT / KCTA
#define ROWS_T 49              // ROWS_CTA / 4

#define BLOCKS_S 98            // scale CTAs per batch
#define F4_PER_B ((size_t)HWT * F4_PER_ROW)        // 802816
#define F4_PER_SCTA (F4_PER_B / BLOCKS_S)          // 8192

__device__ float g_psum[BB][KCTA][CC];
__device__ float g_pmax[BB][KCTA][CC];
__device__ float g_scale[BB][CC];
__device__ int   g_cnt[BB];    // zero-initialized at module load; self-resetting

// Kernel A: pool 8 batches + fan-in MLP tail. grid (KCTA, GROUP), 256 thr.
__global__ void __launch_bounds__(256) pool_mlp_kernel(
    const float* __restrict__ x,
    const float* __restrict__ w1, const float* __restrict__ b1,
    const float* __restrict__ w2, const float* __restrict__ b2,
    int b0)
{
    const int b   = b0 + blockIdx.y;
    const int k   = blockIdx.x;
    const int tid = threadIdx.x;
    const int c4  = tid & 63;
    const int rg  = tid >> 6;

    __shared__ float4 s_sum[4][64];
    __shared__ float4 s_mx4[4][64];
    __shared__ int    s_last;

    const size_t row0 = (size_t)b * HWT + (size_t)k * ROWS_CTA + (size_t)rg * ROWS_T;
    const float4* __restrict__ xp = reinterpret_cast<const float4*>(x) + row0 * F4_PER_ROW + c4;

    float4 s = make_float4(0.f, 0.f, 0.f, 0.f);
    float4 m = make_float4(-INFINITY, -INFINITY, -INFINITY, -INFINITY);
    #pragma unroll 7
    for (int r = 0; r < ROWS_T; ++r) {
        float4 v = xp[(size_t)r * F4_PER_ROW];
        s.x += v.x; s.y += v.y; s.z += v.z; s.w += v.w;
        m.x = fmaxf(m.x, v.x); m.y = fmaxf(m.y, v.y);
        m.z = fmaxf(m.z, v.z); m.w = fmaxf(m.w, v.w);
    }
    s_sum[rg][c4] = s;
    s_mx4[rg][c4] = m;
    __syncthreads();

    if (rg == 0) {
        float4 a0 = s_sum[0][c4], a1 = s_sum[1][c4], a2 = s_sum[2][c4], a3 = s_sum[3][c4];
        float4 m0 = s_mx4[0][c4], m1 = s_mx4[1][c4], m2 = s_mx4[2][c4], m3 = s_mx4[3][c4];
        float4 ss = make_float4(a0.x + a1.x + a2.x + a3.x,
                                a0.y + a1.y + a2.y + a3.y,
                                a0.z + a1.z + a2.z + a3.z,
                                a0.w + a1.w + a2.w + a3.w);
        float4 mm = make_float4(fmaxf(fmaxf(m0.x, m1.x), fmaxf(m2.x, m3.x)),
                                fmaxf(fmaxf(m0.y, m1.y), fmaxf(m2.y, m3.y)),
                                fmaxf(fmaxf(m0.z, m1.z), fmaxf(m2.z, m3.z)),
                                fmaxf(fmaxf(m0.w, m1.w), fmaxf(m2.w, m3.w)));
        reinterpret_cast<float4*>(&g_psum[b][k][0])[c4] = ss;
        reinterpret_cast<float4*>(&g_pmax[b][k][0])[c4] = mm;
    }
    __threadfence();           // release partials
    __syncthreads();

    if (tid == 0) {
        int old = atomicAdd(&g_cnt[b], 1);
        s_last = (old == KCTA - 1);
        if (s_last) {
            g_cnt[b] = 0;      // self-reset for next graph replay
            __threadfence();   // acquire all partials
        }
    }
    __syncthreads();
    if (!s_last) return;

    // ---- fan-in tail: reduce KCTA partials + dual-branch MLP + sigmoid ----
    __shared__ float s_avg[CC];
    __shared__ float s_max[CC];
    __shared__ float s_h[2 * HID];

    float sum = 0.f, mx = -INFINITY;
    #pragma unroll 8
    for (int q = 0; q < KCTA; ++q) {
        sum += __ldcg(&g_psum[b][q][tid]);
        mx = fmaxf(mx, __ldcg(&g_pmax[b][q][tid]));
    }
    s_avg[tid] = sum * (1.0f / (float)HWT);
    s_max[tid] = mx;
    __syncthreads();

    // hidden layer: 64 outputs (avg-branch 0..31, max-branch 32..63), 4 thr/output
    {
        int oi = tid >> 2;
        int part = tid & 3;
        int j = oi & (HID - 1);
        const float* pool = (oi < HID) ? s_avg : s_max;
        float acc = 0.f;
        #pragma unroll 16
        for (int i = part * 64; i < part * 64 + 64; ++i)
            acc += pool[i] * w1[i * HID + j];
        acc += __shfl_down_sync(0xffffffffu, acc, 1);
        acc += __shfl_down_sync(0xffffffffu, acc, 2);
        if (part == 0) s_h[oi] = fmaxf(acc + b1[j], 0.f);
    }
    __syncthreads();

    // output layer: 2*b2 + (hA+hM) @ w2, sigmoid
    {
        float acc = 2.0f * b2[tid];
        #pragma unroll
        for (int j = 0; j < HID; ++j)
            acc += (s_h[j] + s_h[HID + j]) * w2[j * CC + tid];
        g_scale[b][tid] = 1.0f / (1.0f + expf(-acc));
    }
}

// Kernel B: out = x * scale. grid (BLOCKS_S, GROUP), 256 thr. x re-read hits L2.
__global__ void __launch_bounds__(256) scale_kernel(const float* __restrict__ x,
                                                    float* __restrict__ out,
                                                    int b0) {
    const int b   = b0 + blockIdx.y;
    const int tid = threadIdx.x;
    const float4 sc = reinterpret_cast<const float4*>(&g_scale[b][0])[tid & 63];

    const size_t base = (size_t)b * F4_PER_B + (size_t)blockIdx.x * F4_PER_SCTA;
    const float4* __restrict__ xi = reinterpret_cast<const float4*>(x) + base;
    float4* __restrict__ xo = reinterpret_cast<float4*>(out) + base;

    #pragma unroll 8
    for (int i = tid; i < F4_PER_SCTA; i += 256) {
        float4 v = __ldcs(xi + i);                 // last use: evict-first
        v.x *= sc.x; v.y *= sc.y; v.z *= sc.z; v.w *= sc.w;
        __stcs(xo + i, v);                         // streaming store
    }
}

extern "C" void kernel_launch(void* const* d_in, const int* in_sizes, int n_in,
                              void* d_out, int out_size) {
    const float* x  = (const float*)d_in[0];
    const float* w1 = (const float*)d_in[1];
    const float* b1 = (const float*)d_in[2];
    const float* w2 = (const float*)d_in[3];
    const float* b2 = (const float*)d_in[4];
    float* out = (float*)d_out;

    for (int g = 0; g < NGRP; ++g) {
        int b0 = g * GROUP;
        pool_mlp_kernel<<<dim3(KCTA, GROUP), 256>>>(x, w1, b1, w2, b2, b0);
        scale_kernel<<<dim3(BLOCKS_S, GROUP), 256>>>(x, out, b0);
    }
}